// round 6
// baseline (speedup 1.0000x reference)
#include <cuda_runtime.h>
#include <cstdint>

// Problem constants (shapes fixed by the dataset)
#define MAXN 20000
#define MAXE 320000

// ---------------------------------------------------------------------------
// Scratch (device globals; no allocation allowed)
// ---------------------------------------------------------------------------
__device__ float g_deg_inv[MAXN];
__device__ int   g_cnt[MAXN + 1];
__device__ int   g_row_ptr[MAXN + 1];
__device__ int   g_cursor[MAXN];
__device__ int   g_col[MAXE];          // src node per CSR slot (grouped by dst)
__device__ float g_bufH[(size_t)MAXN * 1536];   // layer activations
__device__ float g_bufV[(size_t)MAXN * 768];    // neighbor term (pre-agg)
__device__ float g_bufS[(size_t)MAXN * 768];    // self term
__device__ float g_bufA[(size_t)MAXN * 768];    // layer-1 aggregated x
__device__ int   g_src[MAXE];
__device__ int   g_dst[MAXE];
__device__ int   g_is64;

static inline int cdiv(long long a, long long b) { return (int)((a + b - 1) / b); }

// ---------------------------------------------------------------------------
// Edge index dtype detection + conversion (int64 vs int32 storage)
// ---------------------------------------------------------------------------
__global__ void detect_kernel(const int* __restrict__ raw) {
    if (threadIdx.x == 0 && blockIdx.x == 0) {
        // int64 little-endian: odd 32-bit words are high words == 0 (idx < 2^31)
        int is64 = 1;
        for (int i = 0; i < 64; i++)
            if (raw[2 * i + 1] != 0) { is64 = 0; break; }
        g_is64 = is64;
    }
}

__global__ void convert_kernel(const void* __restrict__ raw,
                               int* __restrict__ src, int* __restrict__ dst, int E) {
    int i = blockIdx.x * blockDim.x + threadIdx.x;
    if (i >= E) return;
    if (g_is64) {
        const long long* p = (const long long*)raw;
        src[i] = (int)p[i];
        dst[i] = (int)p[E + i];
    } else {
        const int* p = (const int*)raw;
        src[i] = p[i];
        dst[i] = p[E + i];
    }
}

// ---------------------------------------------------------------------------
// CSR build: count -> scan -> fill; also deg_inv
// ---------------------------------------------------------------------------
__global__ void count_kernel(const int* __restrict__ dst, int* __restrict__ cnt, int E) {
    int e = blockIdx.x * blockDim.x + threadIdx.x;
    if (e < E) atomicAdd(&cnt[dst[e]], 1);
}

__global__ void deg_inv_kernel(const int* __restrict__ cnt, float* __restrict__ deg_inv, int N) {
    int n = blockIdx.x * blockDim.x + threadIdx.x;
    if (n < N) deg_inv[n] = 1.f / fmaxf((float)cnt[n], 1.f);
}

// single-block exclusive scan over N
__global__ void scan_kernel(const int* __restrict__ cnt, int* __restrict__ row_ptr, int N) {
    __shared__ int s[1024];
    __shared__ int carry;
    if (threadIdx.x == 0) carry = 0;
    __syncthreads();
    for (int base = 0; base < N; base += 1024) {
        int i = base + (int)threadIdx.x;
        int v = (i < N) ? cnt[i] : 0;
        s[threadIdx.x] = v;
        __syncthreads();
#pragma unroll
        for (int off = 1; off < 1024; off <<= 1) {
            int t = (threadIdx.x >= (unsigned)off) ? s[threadIdx.x - off] : 0;
            __syncthreads();
            s[threadIdx.x] += t;
            __syncthreads();
        }
        if (i < N) row_ptr[i] = carry + s[threadIdx.x] - v;  // exclusive
        __syncthreads();
        if (threadIdx.x == 1023) carry += s[1023];
        __syncthreads();
    }
    if (threadIdx.x == 0) row_ptr[N] = carry;
}

__global__ void fill_kernel(const int* __restrict__ src, const int* __restrict__ dst,
                            const int* __restrict__ row_ptr, int* __restrict__ cursor,
                            int* __restrict__ col, int E) {
    int e = blockIdx.x * blockDim.x + threadIdx.x;
    if (e >= E) return;
    int d = dst[e];
    int pos = atomicAdd(&cursor[d], 1);
    col[row_ptr[d] + pos] = src[e];
}

// ---------------------------------------------------------------------------
// Gather-mean over CSR (vectorized float4). out[n] = mean_{s in nbr(n)} v[s]
// Optionally fuses: out = maybe_relu(mean + sterm).
// ---------------------------------------------------------------------------
__global__ void gather_mean4_kernel(const float* __restrict__ v,
                                    const int* __restrict__ rp,
                                    const int* __restrict__ col,
                                    const float* __restrict__ deg_inv,
                                    const float* __restrict__ sterm,  // may be null
                                    float* __restrict__ out,
                                    int N, int F4, int relu) {
    long long idx = (long long)blockIdx.x * blockDim.x + threadIdx.x;
    long long total = (long long)N * F4;
    if (idx >= total) return;
    int n  = (int)(idx / F4);
    int f4 = (int)(idx % F4);
    const int p0 = __ldg(&rp[n]);
    const int p1 = __ldg(&rp[n + 1]);
    const float di = __ldg(&deg_inv[n]);
    const float4* v4 = reinterpret_cast<const float4*>(v);
    float4 acc = make_float4(0.f, 0.f, 0.f, 0.f);
    for (int p = p0; p < p1; p++) {
        int s = __ldg(&col[p]);
        float4 xv = __ldg(&v4[(size_t)s * F4 + f4]);
        acc.x += xv.x; acc.y += xv.y; acc.z += xv.z; acc.w += xv.w;
    }
    acc.x *= di; acc.y *= di; acc.z *= di; acc.w *= di;
    if (sterm) {
        float4 sv = reinterpret_cast<const float4*>(sterm)[idx];
        acc.x += sv.x; acc.y += sv.y; acc.z += sv.z; acc.w += sv.w;
    }
    if (relu) {
        acc.x = fmaxf(acc.x, 0.f); acc.y = fmaxf(acc.y, 0.f);
        acc.z = fmaxf(acc.z, 0.f); acc.w = fmaxf(acc.w, 0.f);
    }
    reinterpret_cast<float4*>(out)[idx] = acc;
}

// scalar variant for small/odd F (layer 5, F=5)
__global__ void gather_mean_kernel(const float* __restrict__ v,
                                   const int* __restrict__ rp,
                                   const int* __restrict__ col,
                                   const float* __restrict__ deg_inv,
                                   const float* __restrict__ sterm,
                                   float* __restrict__ out,
                                   int N, int F, int relu) {
    long long idx = (long long)blockIdx.x * blockDim.x + threadIdx.x;
    long long total = (long long)N * F;
    if (idx >= total) return;
    int n = (int)(idx / F);
    int f = (int)(idx % F);
    int p0 = rp[n], p1 = rp[n + 1];
    float acc = 0.f;
    for (int p = p0; p < p1; p++)
        acc += __ldg(&v[(size_t)__ldg(&col[p]) * F + f]);
    acc *= deg_inv[n];
    if (sterm) acc += sterm[idx];
    if (relu) acc = fmaxf(acc, 0.f);
    out[idx] = acc;
}

// ---------------------------------------------------------------------------
// TF32 tensor-core GEMM with 3-term precision split.
// C = maybe_relu( A @ W [+ A2 @ W2] + bias ),  A:[N,K] rm, W:[K,M] rm.
// Tile 128x128, BK=16, 256 threads (8 warps as 2x4), warp tile 64x32,
// mma.sync.m16n8k8 tf32. Requires K%16==0, M%128==0.
// ---------------------------------------------------------------------------
#define ASP 133   // As row pad (conflict-free transposed stores)
#define BSP 132   // Bs row pad (16B-aligned float4 stores)

struct TC { int g, t, wm, wn; };

__device__ __forceinline__ TC make_tc() {
    TC c;
    int tid = threadIdx.x;
    int lane = tid & 31;
    int warp = tid >> 5;
    c.wm = (warp & 1) * 64;   // 2 warps along M
    c.wn = (warp >> 1) * 32;  // 4 warps along N
    c.g = lane >> 2;          // 0..7
    c.t = lane & 3;           // 0..3
    return c;
}

__device__ __forceinline__ unsigned f2tf32(float x) {
    unsigned r;
    asm("cvt.rna.tf32.f32 %0, %1;" : "=r"(r) : "f"(x));
    return r;
}

__device__ __forceinline__ void split_tf32(float x, unsigned& hi, unsigned& lo) {
    hi = f2tf32(x);
    float l = x - __uint_as_float(hi);   // exact in fp32
    lo = f2tf32(l);
}

__device__ __forceinline__ void mma_tf32(float* c, const unsigned* a, const unsigned* b) {
    asm volatile(
        "mma.sync.aligned.m16n8k8.row.col.f32.tf32.tf32.f32 "
        "{%0,%1,%2,%3}, {%4,%5,%6,%7}, {%8,%9}, {%0,%1,%2,%3};"
        : "+f"(c[0]), "+f"(c[1]), "+f"(c[2]), "+f"(c[3])
        : "r"(a[0]), "r"(a[1]), "r"(a[2]), "r"(a[3]), "r"(b[0]), "r"(b[1]));
}

// Stage one 128x16 A tile (transposed -> As[k][m]) and 16x128 W tile (Bs[k][n]).
__device__ __forceinline__ void load_tiles(
    const float* __restrict__ A, const float* __restrict__ W,
    int N, int K, int M, int r0, int c0, int k0,
    float (*As)[ASP], float (*Bs)[BSP]) {
    const int tid = threadIdx.x;
#pragma unroll
    for (int tl = 0; tl < 2; tl++) {
        int i = tid + tl * 256;          // 0..511 float4 slots
        // A: 128 rows x 16 k
        int row = i >> 2;
        int cg = (i & 3) * 4;
        float4 av = make_float4(0.f, 0.f, 0.f, 0.f);
        int gr = r0 + row;
        if (gr < N)
            av = *reinterpret_cast<const float4*>(A + (size_t)gr * K + k0 + cg);
        As[cg + 0][row] = av.x;
        As[cg + 1][row] = av.y;
        As[cg + 2][row] = av.z;
        As[cg + 3][row] = av.w;
        // W: 16 k-rows x 128 cols
        int kr = i >> 5;
        int nc = (i & 31) * 4;
        float4 bv = *reinterpret_cast<const float4*>(
            W + (size_t)(k0 + kr) * M + c0 + nc);
        *reinterpret_cast<float4*>(&Bs[kr][nc]) = bv;
    }
}

__device__ __forceinline__ void compute_ktile(
    const TC& tc, float (*As)[ASP], float (*Bs)[BSP], float acc[4][4][4]) {
#pragma unroll
    for (int ks = 0; ks < 16; ks += 8) {
        unsigned bh[4][2], bl[4][2];
#pragma unroll
        for (int nt = 0; nt < 4; nt++)
#pragma unroll
            for (int kk = 0; kk < 2; kk++) {
                float bv = Bs[ks + tc.t + kk * 4][tc.wn + nt * 8 + tc.g];
                split_tf32(bv, bh[nt][kk], bl[nt][kk]);
            }
#pragma unroll
        for (int mt = 0; mt < 4; mt++) {
            int m0 = tc.wm + mt * 16 + tc.g;
            // m16n8k8 A frags: a0=(g,t) a1=(g+8,t) a2=(g,t+4) a3=(g+8,t+4)
            float a0 = As[ks + tc.t][m0];
            float a1 = As[ks + tc.t][m0 + 8];
            float a2 = As[ks + tc.t + 4][m0];
            float a3 = As[ks + tc.t + 4][m0 + 8];
            unsigned ah[4], al[4];
            split_tf32(a0, ah[0], al[0]);
            split_tf32(a1, ah[1], al[1]);
            split_tf32(a2, ah[2], al[2]);
            split_tf32(a3, ah[3], al[3]);
#pragma unroll
            for (int nt = 0; nt < 4; nt++) {
                mma_tf32(acc[mt][nt], ah, bh[nt]);  // hi*hi
                mma_tf32(acc[mt][nt], ah, bl[nt]);  // hi*lo
                mma_tf32(acc[mt][nt], al, bh[nt]);  // lo*hi
            }
        }
    }
}

__device__ __forceinline__ void tgemm_pass(
    const float* __restrict__ A, const float* __restrict__ W,
    int N, int K, int M, int r0, int c0, const TC& tc,
    float acc[4][4][4], float (*As)[16][ASP], float (*Bs)[16][BSP]) {
    const int nT = K >> 4;
    int buf = 0;
    load_tiles(A, W, N, K, M, r0, c0, 0, As[0], Bs[0]);
    __syncthreads();
#pragma unroll 1
    for (int ti = 0; ti < nT; ti++) {
        if (ti + 1 < nT)
            load_tiles(A, W, N, K, M, r0, c0, (ti + 1) * 16,
                       As[buf ^ 1], Bs[buf ^ 1]);
        compute_ktile(tc, As[buf], Bs[buf], acc);
        __syncthreads();
        buf ^= 1;
    }
}

__device__ __forceinline__ void tgemm_epilogue(
    float acc[4][4][4], const float* __restrict__ bias,
    float* __restrict__ C, int N, int M, int r0, int c0,
    const TC& tc, int relu) {
#pragma unroll
    for (int mt = 0; mt < 4; mt++) {
        int row0 = r0 + tc.wm + mt * 16 + tc.g;
        int row1 = row0 + 8;
#pragma unroll
        for (int nt = 0; nt < 4; nt++) {
            int colg = c0 + tc.wn + nt * 8 + tc.t * 2;
            float b0 = bias ? __ldg(&bias[colg])     : 0.f;
            float b1 = bias ? __ldg(&bias[colg + 1]) : 0.f;
            float v0 = acc[mt][nt][0] + b0;
            float v1 = acc[mt][nt][1] + b1;
            float v2 = acc[mt][nt][2] + b0;
            float v3 = acc[mt][nt][3] + b1;
            if (relu) {
                v0 = fmaxf(v0, 0.f); v1 = fmaxf(v1, 0.f);
                v2 = fmaxf(v2, 0.f); v3 = fmaxf(v3, 0.f);
            }
            if (row0 < N) {
                C[(size_t)row0 * M + colg]     = v0;
                C[(size_t)row0 * M + colg + 1] = v1;
            }
            if (row1 < N) {
                C[(size_t)row1 * M + colg]     = v2;
                C[(size_t)row1 * M + colg + 1] = v3;
            }
        }
    }
}

// Layer-1: C = relu(A1@W1 + A2@W2 + bias)
__global__ __launch_bounds__(256)
void tgemm_dual(const float* __restrict__ A1, const float* __restrict__ W1,
                const float* __restrict__ A2, const float* __restrict__ W2,
                const float* __restrict__ bias, float* __restrict__ C,
                int N, int K, int M, int relu) {
    __shared__ float As[2][16][ASP];
    __shared__ float Bs[2][16][BSP];
    TC tc = make_tc();
    const int r0 = blockIdx.y * 128;
    const int c0 = blockIdx.x * 128;
    float acc[4][4][4];
#pragma unroll
    for (int a = 0; a < 4; a++)
#pragma unroll
        for (int b = 0; b < 4; b++)
#pragma unroll
            for (int c = 0; c < 4; c++) acc[a][b][c] = 0.f;

    tgemm_pass(A1, W1, N, K, M, r0, c0, tc, acc, As, Bs);
    tgemm_pass(A2, W2, N, K, M, r0, c0, tc, acc, As, Bs);
    tgemm_epilogue(acc, bias, C, N, M, r0, c0, tc, relu);
}

// Layers 2-4: one launch computes Cv = A@Wl and Cs = A@Wr + bias.
// gridDim.x = 2*(M/128); first half -> V, second half -> S.
__global__ __launch_bounds__(256)
void tgemm_pair(const float* __restrict__ A,
                const float* __restrict__ Wl, const float* __restrict__ Wr,
                const float* __restrict__ bias,
                float* __restrict__ Cv, float* __restrict__ Cs,
                int N, int K, int M) {
    __shared__ float As[2][16][ASP];
    __shared__ float Bs[2][16][BSP];
    TC tc = make_tc();
    const int halves = gridDim.x >> 1;
    const bool isS = ((int)blockIdx.x >= halves);
    const int bx = isS ? ((int)blockIdx.x - halves) : (int)blockIdx.x;
    const int r0 = blockIdx.y * 128;
    const int c0 = bx * 128;
    const float* W = isS ? Wr : Wl;
    float* C = isS ? Cs : Cv;
    const float* b = isS ? bias : nullptr;

    float acc[4][4][4];
#pragma unroll
    for (int a = 0; a < 4; a++)
#pragma unroll
        for (int bb2 = 0; bb2 < 4; bb2++)
#pragma unroll
            for (int c = 0; c < 4; c++) acc[a][bb2][c] = 0.f;

    tgemm_pass(A, W, N, K, M, r0, c0, tc, acc, As, Bs);
    tgemm_epilogue(acc, b, C, N, M, r0, c0, tc, 0);
}

// ---------------------------------------------------------------------------
// Fallback GEMM (any M/K) — used only for the M=5 final layer (fp32 SIMT)
// ---------------------------------------------------------------------------
__global__ __launch_bounds__(256)
void gemm_small(const float* __restrict__ A, const float* __restrict__ W,
                const float* __restrict__ bias, float* __restrict__ C,
                int N, int K, int M) {
    __shared__ float As[64][16];
    __shared__ float Ws[16][64];

    int tid = threadIdx.x;
    int tx = tid & 15;
    int ty = tid >> 4;
    int row0 = blockIdx.y * 64 + ty * 4;
    int col0 = blockIdx.x * 64 + tx * 4;

    float acc[4][4];
#pragma unroll
    for (int i = 0; i < 4; i++)
#pragma unroll
        for (int j = 0; j < 4; j++) acc[i][j] = 0.f;

    for (int k0 = 0; k0 < K; k0 += 16) {
#pragma unroll
        for (int i = 0; i < 4; i++) {
            int e = tid + i * 256;
            int r = e >> 4, c = e & 15;
            int grr = blockIdx.y * 64 + r;
            As[r][c] = (grr < N && (k0 + c) < K)
                           ? A[(size_t)grr * K + k0 + c] : 0.f;
        }
#pragma unroll
        for (int i = 0; i < 4; i++) {
            int e = tid + i * 256;
            int r = e >> 6, c = e & 63;
            int gc = blockIdx.x * 64 + c;
            Ws[r][c] = (gc < M && (k0 + r) < K)
                           ? W[(size_t)(k0 + r) * M + gc] : 0.f;
        }
        __syncthreads();
#pragma unroll
        for (int kk = 0; kk < 16; kk++) {
            float a[4], b[4];
#pragma unroll
            for (int i = 0; i < 4; i++) a[i] = As[ty * 4 + i][kk];
#pragma unroll
            for (int j = 0; j < 4; j++) b[j] = Ws[kk][tx * 4 + j];
#pragma unroll
            for (int i = 0; i < 4; i++)
#pragma unroll
                for (int j = 0; j < 4; j++)
                    acc[i][j] = fmaf(a[i], b[j], acc[i][j]);
        }
        __syncthreads();
    }

#pragma unroll
    for (int i = 0; i < 4; i++) {
        int r = row0 + i;
        if (r >= N) continue;
#pragma unroll
        for (int j = 0; j < 4; j++) {
            int c = col0 + j;
            if (c >= M) continue;
            float v = acc[i][j];
            if (bias) v += bias[c];
            C[(size_t)r * M + c] = v;
        }
    }
}

// ---------------------------------------------------------------------------
// Host-side launcher
// ---------------------------------------------------------------------------
static void launch_gather(const float* v, const int* rp, const int* col,
                          const float* deg_inv, const float* sterm,
                          float* out, int N, int F, int relu) {
    if ((F & 3) == 0) {
        int F4 = F >> 2;
        long long total = (long long)N * F4;
        gather_mean4_kernel<<<cdiv(total, 256), 256>>>(
            v, rp, col, deg_inv, sterm, out, N, F4, relu);
    } else {
        long long total = (long long)N * F;
        gather_mean_kernel<<<cdiv(total, 256), 256>>>(
            v, rp, col, deg_inv, sterm, out, N, F, relu);
    }
}

extern "C" void kernel_launch(void* const* d_in, const int* in_sizes, int n_in,
                              void* d_out, int out_size) {
    const float* x = (const float*)d_in[0];
    const void* edge_raw = d_in[1];
    const int N = in_sizes[0] / 768;
    const int E = in_sizes[1] / 2;

    const float* Wl[5]; const float* Wr[5]; const float* bb[5];
    for (int li = 0; li < 5; li++) {
        Wl[li] = (const float*)d_in[2 + 3 * li];
        Wr[li] = (const float*)d_in[3 + 3 * li];
        bb[li] = (const float*)d_in[4 + 3 * li];
    }

    float *deg_inv, *bufH, *bufV, *bufS, *bufA;
    int *src, *dst, *cnt, *row_ptr, *cursor, *col;
    cudaGetSymbolAddress((void**)&deg_inv, g_deg_inv);
    cudaGetSymbolAddress((void**)&bufH,    g_bufH);
    cudaGetSymbolAddress((void**)&bufV,    g_bufV);
    cudaGetSymbolAddress((void**)&bufS,    g_bufS);
    cudaGetSymbolAddress((void**)&bufA,    g_bufA);
    cudaGetSymbolAddress((void**)&src,     g_src);
    cudaGetSymbolAddress((void**)&dst,     g_dst);
    cudaGetSymbolAddress((void**)&cnt,     g_cnt);
    cudaGetSymbolAddress((void**)&row_ptr, g_row_ptr);
    cudaGetSymbolAddress((void**)&cursor,  g_cursor);
    cudaGetSymbolAddress((void**)&col,     g_col);

    float* out_h = (float*)d_out;                    // [N, 256]
    float* out_y = (float*)d_out + (size_t)N * 256;  // [N, 5]

    // ---- edge index conversion (int32 or int64 storage) ----
    detect_kernel<<<1, 32>>>((const int*)edge_raw);
    convert_kernel<<<cdiv(E, 256), 256>>>(edge_raw, src, dst, E);

    // ---- CSR build (dst-grouped) + deg_inv ----
    cudaMemsetAsync(cnt, 0, (size_t)(N + 1) * sizeof(int), 0);
    cudaMemsetAsync(cursor, 0, (size_t)N * sizeof(int), 0);
    count_kernel<<<cdiv(E, 256), 256>>>(dst, cnt, E);
    deg_inv_kernel<<<cdiv(N, 256), 256>>>(cnt, deg_inv, N);
    scan_kernel<<<1, 1024>>>(cnt, row_ptr, N);
    fill_kernel<<<cdiv(E, 256), 256>>>(src, dst, row_ptr, cursor, col, E);

    // ---- Layer 1 (768 -> 1536): aggregate-first ----
    // bufA = mean-gather(x); h1 = relu(bufA @ Wl1 + x @ Wr1 + b1)
    launch_gather(x, row_ptr, col, deg_inv, nullptr, bufA, N, 768, 0);
    {
        dim3 grid(1536 / 128, cdiv(N, 128));
        tgemm_dual<<<grid, 256>>>(bufA, Wl[0], x, Wr[0], bb[0], bufH,
                                  N, 768, 1536, 1);
    }

    // ---- Layers 2..5: transform-then-aggregate ----
    const int dims_in[4]  = {1536, 768, 384, 256};
    const int dims_out[4] = {768, 384, 256, 5};
    const float* hin = bufH;
    for (int li = 1; li < 5; li++) {
        int K = dims_in[li - 1];
        int M = dims_out[li - 1];
        if (M % 128 == 0 && K % 16 == 0) {
            // one launch computes V = h@Wl and S = h@Wr + b
            dim3 grid(2 * (M / 128), cdiv(N, 128));
            tgemm_pair<<<grid, 256>>>(hin, Wl[li], Wr[li], bb[li],
                                      bufV, bufS, N, K, M);
        } else {
            dim3 grid(cdiv(M, 64), cdiv(N, 64));
            gemm_small<<<grid, 256>>>(hin, Wl[li], nullptr, bufV, N, K, M);
            gemm_small<<<grid, 256>>>(hin, Wr[li], bb[li],  bufS, N, K, M);
        }
        // out = maybe_relu(mean-gather(V) + S)
        if (li == 3) {
            launch_gather(bufV, row_ptr, col, deg_inv, bufS, out_h, N, M, 1);
            hin = out_h;
        } else if (li == 4) {
            launch_gather(bufV, row_ptr, col, deg_inv, bufS, out_y, N, M, 0);
        } else {
            launch_gather(bufV, row_ptr, col, deg_inv, bufS, bufH, N, M, 1);
            hin = bufH;
        }
    }
}

// round 9
// speedup vs baseline: 1.2792x; 1.2792x over previous
#include <cuda_runtime.h>
#include <cuda_bf16.h>
#include <cstdint>

// Problem constants (shapes fixed by the dataset)
#define MAXN 20000
#define MAXE 320000

// ---------------------------------------------------------------------------
// Scratch (device globals; no allocation allowed)
// ---------------------------------------------------------------------------
__device__ float g_deg_inv[MAXN];
__device__ int   g_cnt[MAXN + 1];
__device__ int   g_row_ptr[MAXN + 1];
__device__ int   g_cursor[MAXN];
__device__ int   g_col[MAXE];          // src node per CSR slot (grouped by dst)
__device__ float g_bufH[(size_t)MAXN * 1536];   // layer activations
__device__ float g_bufV[(size_t)MAXN * 768];    // neighbor term (pre-agg)
__device__ float g_bufS[(size_t)MAXN * 768];    // self term
__device__ float g_bufA[(size_t)MAXN * 768];    // layer-1 aggregated x
__device__ int   g_src[MAXE];
__device__ int   g_dst[MAXE];
__device__ int   g_is64;

static inline int cdiv(long long a, long long b) { return (int)((a + b - 1) / b); }

// ---------------------------------------------------------------------------
// Edge index dtype detection + conversion (int64 vs int32 storage)
// ---------------------------------------------------------------------------
__global__ void detect_kernel(const int* __restrict__ raw) {
    if (threadIdx.x == 0 && blockIdx.x == 0) {
        // int64 little-endian: odd 32-bit words are high words == 0 (idx < 2^31)
        int is64 = 1;
        for (int i = 0; i < 64; i++)
            if (raw[2 * i + 1] != 0) { is64 = 0; break; }
        g_is64 = is64;
    }
}

__global__ void convert_kernel(const void* __restrict__ raw,
                               int* __restrict__ src, int* __restrict__ dst, int E) {
    int i = blockIdx.x * blockDim.x + threadIdx.x;
    if (i >= E) return;
    if (g_is64) {
        const long long* p = (const long long*)raw;
        src[i] = (int)p[i];
        dst[i] = (int)p[E + i];
    } else {
        const int* p = (const int*)raw;
        src[i] = p[i];
        dst[i] = p[E + i];
    }
}

// ---------------------------------------------------------------------------
// CSR build: count -> scan -> fill; also deg_inv
// ---------------------------------------------------------------------------
__global__ void count_kernel(const int* __restrict__ dst, int* __restrict__ cnt, int E) {
    int e = blockIdx.x * blockDim.x + threadIdx.x;
    if (e < E) atomicAdd(&cnt[dst[e]], 1);
}

__global__ void deg_inv_kernel(const int* __restrict__ cnt, float* __restrict__ deg_inv, int N) {
    int n = blockIdx.x * blockDim.x + threadIdx.x;
    if (n < N) deg_inv[n] = 1.f / fmaxf((float)cnt[n], 1.f);
}

// single-block exclusive scan over N
__global__ void scan_kernel(const int* __restrict__ cnt, int* __restrict__ row_ptr, int N) {
    __shared__ int s[1024];
    __shared__ int carry;
    if (threadIdx.x == 0) carry = 0;
    __syncthreads();
    for (int base = 0; base < N; base += 1024) {
        int i = base + (int)threadIdx.x;
        int v = (i < N) ? cnt[i] : 0;
        s[threadIdx.x] = v;
        __syncthreads();
#pragma unroll
        for (int off = 1; off < 1024; off <<= 1) {
            int t = (threadIdx.x >= (unsigned)off) ? s[threadIdx.x - off] : 0;
            __syncthreads();
            s[threadIdx.x] += t;
            __syncthreads();
        }
        if (i < N) row_ptr[i] = carry + s[threadIdx.x] - v;  // exclusive
        __syncthreads();
        if (threadIdx.x == 1023) carry += s[1023];
        __syncthreads();
    }
    if (threadIdx.x == 0) row_ptr[N] = carry;
}

__global__ void fill_kernel(const int* __restrict__ src, const int* __restrict__ dst,
                            const int* __restrict__ row_ptr, int* __restrict__ cursor,
                            int* __restrict__ col, int E) {
    int e = blockIdx.x * blockDim.x + threadIdx.x;
    if (e >= E) return;
    int d = dst[e];
    int pos = atomicAdd(&cursor[d], 1);
    col[row_ptr[d] + pos] = src[e];
}

// ---------------------------------------------------------------------------
// Gather-mean over CSR (vectorized float4). out[n] = mean_{s in nbr(n)} v[s]
// Optionally fuses: out = maybe_relu(mean + sterm).
// ---------------------------------------------------------------------------
__global__ void gather_mean4_kernel(const float* __restrict__ v,
                                    const int* __restrict__ rp,
                                    const int* __restrict__ col,
                                    const float* __restrict__ deg_inv,
                                    const float* __restrict__ sterm,  // may be null
                                    float* __restrict__ out,
                                    int N, int F4, int relu) {
    long long idx = (long long)blockIdx.x * blockDim.x + threadIdx.x;
    long long total = (long long)N * F4;
    if (idx >= total) return;
    int n  = (int)(idx / F4);
    int f4 = (int)(idx % F4);
    const int p0 = __ldg(&rp[n]);
    const int p1 = __ldg(&rp[n + 1]);
    const float di = __ldg(&deg_inv[n]);
    const float4* v4 = reinterpret_cast<const float4*>(v);
    float4 acc = make_float4(0.f, 0.f, 0.f, 0.f);
    for (int p = p0; p < p1; p++) {
        int s = __ldg(&col[p]);
        float4 xv = __ldg(&v4[(size_t)s * F4 + f4]);
        acc.x += xv.x; acc.y += xv.y; acc.z += xv.z; acc.w += xv.w;
    }
    acc.x *= di; acc.y *= di; acc.z *= di; acc.w *= di;
    if (sterm) {
        float4 sv = reinterpret_cast<const float4*>(sterm)[idx];
        acc.x += sv.x; acc.y += sv.y; acc.z += sv.z; acc.w += sv.w;
    }
    if (relu) {
        acc.x = fmaxf(acc.x, 0.f); acc.y = fmaxf(acc.y, 0.f);
        acc.z = fmaxf(acc.z, 0.f); acc.w = fmaxf(acc.w, 0.f);
    }
    reinterpret_cast<float4*>(out)[idx] = acc;
}

// scalar variant for small/odd F (layer 5, F=5)
__global__ void gather_mean_kernel(const float* __restrict__ v,
                                   const int* __restrict__ rp,
                                   const int* __restrict__ col,
                                   const float* __restrict__ deg_inv,
                                   const float* __restrict__ sterm,
                                   float* __restrict__ out,
                                   int N, int F, int relu) {
    long long idx = (long long)blockIdx.x * blockDim.x + threadIdx.x;
    long long total = (long long)N * F;
    if (idx >= total) return;
    int n = (int)(idx / F);
    int f = (int)(idx % F);
    int p0 = rp[n], p1 = rp[n + 1];
    float acc = 0.f;
    for (int p = p0; p < p1; p++)
        acc += __ldg(&v[(size_t)__ldg(&col[p]) * F + f]);
    acc *= deg_inv[n];
    if (sterm) acc += sterm[idx];
    if (relu) acc = fmaxf(acc, 0.f);
    out[idx] = acc;
}

// ---------------------------------------------------------------------------
// BF16 tensor-core GEMM with 3-term precision split (hi*hi + hi*lo + lo*hi),
// split precomputed at tile staging. C = maybe_relu(A@W [+ A2@W2] + bias).
// A:[N,K] rm, W:[K,M] rm. Tile 128x128, BK=16, 256 thr (8 warps as 2x4),
// warp tile 64x32, mma.sync.m16n8k16 bf16. Requires K%16==0, M%128==0.
// smem: As*[m][k/2] u32 (2 bf16 = consecutive k), Bs*[n][k/2] u32.
// ---------------------------------------------------------------------------
#define KP 10   // u32 pitch per 16-k row (8 used + 2 pad)

struct TC { int g, t, wm, wn; };

__device__ __forceinline__ TC make_tc() {
    TC c;
    int tid = threadIdx.x;
    int lane = tid & 31;
    int warp = tid >> 5;
    c.wm = (warp & 1) * 64;   // 2 warps along M
    c.wn = (warp >> 1) * 32;  // 4 warps along N
    c.g = lane >> 2;          // 0..7
    c.t = lane & 3;           // 0..3
    return c;
}

__device__ __forceinline__ void split2(float x, float y,
                                       unsigned& hi, unsigned& lo) {
    __nv_bfloat16 hx = __float2bfloat16_rn(x);
    __nv_bfloat16 hy = __float2bfloat16_rn(y);
    float rx = x - __bfloat162float(hx);
    float ry = y - __bfloat162float(hy);
    __nv_bfloat16 lx = __float2bfloat16_rn(rx);
    __nv_bfloat16 ly = __float2bfloat16_rn(ry);
    hi = ((unsigned)__bfloat16_as_ushort(hy) << 16) | __bfloat16_as_ushort(hx);
    lo = ((unsigned)__bfloat16_as_ushort(ly) << 16) | __bfloat16_as_ushort(lx);
}

__device__ __forceinline__ void mma_bf16(float* c, const unsigned* a,
                                         const unsigned* b) {
    asm volatile(
        "mma.sync.aligned.m16n8k16.row.col.f32.bf16.bf16.f32 "
        "{%0,%1,%2,%3}, {%4,%5,%6,%7}, {%8,%9}, {%0,%1,%2,%3};"
        : "+f"(c[0]), "+f"(c[1]), "+f"(c[2]), "+f"(c[3])
        : "r"(a[0]), "r"(a[1]), "r"(a[2]), "r"(a[3]), "r"(b[0]), "r"(b[1]));
}

// Stage one 128x16 A tile and 16x128 W tile, pre-split into bf16 hi/lo.
__device__ __forceinline__ void load_tiles16(
    const float* __restrict__ A, const float* __restrict__ W,
    int N, int K, int M, int r0, int c0, int k0,
    unsigned (*AsH)[KP], unsigned (*AsL)[KP],
    unsigned (*BsH)[KP], unsigned (*BsL)[KP]) {
    const int tid = threadIdx.x;
    // A: 128 rows x 16 k, float4 per thread x2
#pragma unroll
    for (int tl = 0; tl < 2; tl++) {
        int i = tid + tl * 256;          // 0..511
        int row = i >> 2;
        int cg = (i & 3) * 4;            // k offset 0,4,8,12
        float4 av = make_float4(0.f, 0.f, 0.f, 0.f);
        int gr = r0 + row;
        if (gr < N)
            av = *reinterpret_cast<const float4*>(A + (size_t)gr * K + k0 + cg);
        unsigned h0, l0, h1, l1;
        split2(av.x, av.y, h0, l0);
        split2(av.z, av.w, h1, l1);
        int kq = cg >> 1;
        AsH[row][kq]     = h0;
        AsH[row][kq + 1] = h1;
        AsL[row][kq]     = l0;
        AsL[row][kq + 1] = l1;
    }
    // W: 16 k-rows x 128 cols -> transposed [n][k/2]; 2 floats (consec k) per slot
#pragma unroll
    for (int tl = 0; tl < 4; tl++) {
        int i = tid + tl * 256;          // 0..1023
        int n = i & 127;
        int kp = i >> 7;                 // 0..7
        float w0 = __ldg(W + (size_t)(k0 + 2 * kp)     * M + c0 + n);
        float w1 = __ldg(W + (size_t)(k0 + 2 * kp + 1) * M + c0 + n);
        unsigned h, l;
        split2(w0, w1, h, l);
        BsH[n][kp] = h;
        BsL[n][kp] = l;
    }
}

__device__ __forceinline__ void compute_ktile16(
    const TC& tc,
    unsigned (*AsH)[KP], unsigned (*AsL)[KP],
    unsigned (*BsH)[KP], unsigned (*BsL)[KP],
    float acc[4][4][4]) {
    unsigned bh[4][2], bl[4][2];
#pragma unroll
    for (int nt = 0; nt < 4; nt++) {
        int n0 = tc.wn + nt * 8 + tc.g;
        bh[nt][0] = BsH[n0][tc.t];
        bh[nt][1] = BsH[n0][tc.t + 4];
        bl[nt][0] = BsL[n0][tc.t];
        bl[nt][1] = BsL[n0][tc.t + 4];
    }
#pragma unroll
    for (int mt = 0; mt < 4; mt++) {
        int m0 = tc.wm + mt * 16 + tc.g;
        // m16n8k16 A frags: a0=(g, 2t..2t+1) a1=(g+8, ..) a2=(g, 2t+8..9) a3=(g+8, ..)
        unsigned ah[4], al[4];
        ah[0] = AsH[m0][tc.t];     ah[1] = AsH[m0 + 8][tc.t];
        ah[2] = AsH[m0][tc.t + 4]; ah[3] = AsH[m0 + 8][tc.t + 4];
        al[0] = AsL[m0][tc.t];     al[1] = AsL[m0 + 8][tc.t];
        al[2] = AsL[m0][tc.t + 4]; al[3] = AsL[m0 + 8][tc.t + 4];
#pragma unroll
        for (int nt = 0; nt < 4; nt++) {
            mma_bf16(acc[mt][nt], ah, bh[nt]);  // hi*hi
            mma_bf16(acc[mt][nt], ah, bl[nt]);  // hi*lo
            mma_bf16(acc[mt][nt], al, bh[nt]);  // lo*hi
        }
    }
}

__device__ __forceinline__ void tgemm_pass(
    const float* __restrict__ A, const float* __restrict__ W,
    int N, int K, int M, int r0, int c0, const TC& tc,
    float acc[4][4][4],
    unsigned (*AsH)[128][KP], unsigned (*AsL)[128][KP],
    unsigned (*BsH)[128][KP], unsigned (*BsL)[128][KP]) {
    const int nT = K >> 4;
    int buf = 0;
    load_tiles16(A, W, N, K, M, r0, c0, 0, AsH[0], AsL[0], BsH[0], BsL[0]);
    __syncthreads();
#pragma unroll 1
    for (int ti = 0; ti < nT; ti++) {
        if (ti + 1 < nT)
            load_tiles16(A, W, N, K, M, r0, c0, (ti + 1) * 16,
                         AsH[buf ^ 1], AsL[buf ^ 1], BsH[buf ^ 1], BsL[buf ^ 1]);
        compute_ktile16(tc, AsH[buf], AsL[buf], BsH[buf], BsL[buf], acc);
        __syncthreads();
        buf ^= 1;
    }
}

__device__ __forceinline__ void tgemm_epilogue(
    float acc[4][4][4], const float* __restrict__ bias,
    float* __restrict__ C, int N, int M, int r0, int c0,
    const TC& tc, int relu) {
#pragma unroll
    for (int mt = 0; mt < 4; mt++) {
        int row0 = r0 + tc.wm + mt * 16 + tc.g;
        int row1 = row0 + 8;
#pragma unroll
        for (int nt = 0; nt < 4; nt++) {
            int colg = c0 + tc.wn + nt * 8 + tc.t * 2;
            float b0 = bias ? __ldg(&bias[colg])     : 0.f;
            float b1 = bias ? __ldg(&bias[colg + 1]) : 0.f;
            float v0 = acc[mt][nt][0] + b0;
            float v1 = acc[mt][nt][1] + b1;
            float v2 = acc[mt][nt][2] + b0;
            float v3 = acc[mt][nt][3] + b1;
            if (relu) {
                v0 = fmaxf(v0, 0.f); v1 = fmaxf(v1, 0.f);
                v2 = fmaxf(v2, 0.f); v3 = fmaxf(v3, 0.f);
            }
            if (row0 < N) {
                C[(size_t)row0 * M + colg]     = v0;
                C[(size_t)row0 * M + colg + 1] = v1;
            }
            if (row1 < N) {
                C[(size_t)row1 * M + colg]     = v2;
                C[(size_t)row1 * M + colg + 1] = v3;
            }
        }
    }
}

// Layer-1: C = relu(A1@W1 + A2@W2 + bias)
__global__ __launch_bounds__(256)
void tgemm_dual(const float* __restrict__ A1, const float* __restrict__ W1,
                const float* __restrict__ A2, const float* __restrict__ W2,
                const float* __restrict__ bias, float* __restrict__ C,
                int N, int K, int M, int relu) {
    __shared__ unsigned AsH[2][128][KP];
    __shared__ unsigned AsL[2][128][KP];
    __shared__ unsigned BsH[2][128][KP];
    __shared__ unsigned BsL[2][128][KP];
    TC tc = make_tc();
    const int r0 = blockIdx.y * 128;
    const int c0 = blockIdx.x * 128;
    float acc[4][4][4];
#pragma unroll
    for (int a = 0; a < 4; a++)
#pragma unroll
        for (int b = 0; b < 4; b++)
#pragma unroll
            for (int c = 0; c < 4; c++) acc[a][b][c] = 0.f;

    tgemm_pass(A1, W1, N, K, M, r0, c0, tc, acc, AsH, AsL, BsH, BsL);
    tgemm_pass(A2, W2, N, K, M, r0, c0, tc, acc, AsH, AsL, BsH, BsL);
    tgemm_epilogue(acc, bias, C, N, M, r0, c0, tc, relu);
}

// Layers 2-4: one launch computes Cv = A@Wl and Cs = A@Wr + bias.
__global__ __launch_bounds__(256)
void tgemm_pair(const float* __restrict__ A,
                const float* __restrict__ Wl, const float* __restrict__ Wr,
                const float* __restrict__ bias,
                float* __restrict__ Cv, float* __restrict__ Cs,
                int N, int K, int M) {
    __shared__ unsigned AsH[2][128][KP];
    __shared__ unsigned AsL[2][128][KP];
    __shared__ unsigned BsH[2][128][KP];
    __shared__ unsigned BsL[2][128][KP];
    TC tc = make_tc();
    const int halves = gridDim.x >> 1;
    const bool isS = ((int)blockIdx.x >= halves);
    const int bx = isS ? ((int)blockIdx.x - halves) : (int)blockIdx.x;
    const int r0 = blockIdx.y * 128;
    const int c0 = bx * 128;
    const float* W = isS ? Wr : Wl;
    float* C = isS ? Cs : Cv;
    const float* b = isS ? bias : nullptr;

    float acc[4][4][4];
#pragma unroll
    for (int a = 0; a < 4; a++)
#pragma unroll
        for (int bb2 = 0; bb2 < 4; bb2++)
#pragma unroll
            for (int c = 0; c < 4; c++) acc[a][bb2][c] = 0.f;

    tgemm_pass(A, W, N, K, M, r0, c0, tc, acc, AsH, AsL, BsH, BsL);
    tgemm_epilogue(acc, b, C, N, M, r0, c0, tc, 0);
}

// ---------------------------------------------------------------------------
// Fallback GEMM (any M/K) — used only for the M=5 final layer (fp32 SIMT)
// ---------------------------------------------------------------------------
__global__ __launch_bounds__(256)
void gemm_small(const float* __restrict__ A, const float* __restrict__ W,
                const float* __restrict__ bias, float* __restrict__ C,
                int N, int K, int M) {
    __shared__ float As[64][16];
    __shared__ float Ws[16][64];

    int tid = threadIdx.x;
    int tx = tid & 15;
    int ty = tid >> 4;
    int row0 = blockIdx.y * 64 + ty * 4;
    int col0 = blockIdx.x * 64 + tx * 4;

    float acc[4][4];
#pragma unroll
    for (int i = 0; i < 4; i++)
#pragma unroll
        for (int j = 0; j < 4; j++) acc[i][j] = 0.f;

    for (int k0 = 0; k0 < K; k0 += 16) {
#pragma unroll
        for (int i = 0; i < 4; i++) {
            int e = tid + i * 256;
            int r = e >> 4, c = e & 15;
            int grr = blockIdx.y * 64 + r;
            As[r][c] = (grr < N && (k0 + c) < K)
                           ? A[(size_t)grr * K + k0 + c] : 0.f;
        }
#pragma unroll
        for (int i = 0; i < 4; i++) {
            int e = tid + i * 256;
            int r = e >> 6, c = e & 63;
            int gc = blockIdx.x * 64 + c;
            Ws[r][c] = (gc < M && (k0 + r) < K)
                           ? W[(size_t)(k0 + r) * M + gc] : 0.f;
        }
        __syncthreads();
#pragma unroll
        for (int kk = 0; kk < 16; kk++) {
            float a[4], b[4];
#pragma unroll
            for (int i = 0; i < 4; i++) a[i] = As[ty * 4 + i][kk];
#pragma unroll
            for (int j = 0; j < 4; j++) b[j] = Ws[kk][tx * 4 + j];
#pragma unroll
            for (int i = 0; i < 4; i++)
#pragma unroll
                for (int j = 0; j < 4; j++)
                    acc[i][j] = fmaf(a[i], b[j], acc[i][j]);
        }
        __syncthreads();
    }

#pragma unroll
    for (int i = 0; i < 4; i++) {
        int r = row0 + i;
        if (r >= N) continue;
#pragma unroll
        for (int j = 0; j < 4; j++) {
            int c = col0 + j;
            if (c >= M) continue;
            float v = acc[i][j];
            if (bias) v += bias[c];
            C[(size_t)r * M + c] = v;
        }
    }
}

// ---------------------------------------------------------------------------
// Host-side launcher
// ---------------------------------------------------------------------------
static void launch_gather(const float* v, const int* rp, const int* col,
                          const float* deg_inv, const float* sterm,
                          float* out, int N, int F, int relu) {
    if ((F & 3) == 0) {
        int F4 = F >> 2;
        long long total = (long long)N * F4;
        gather_mean4_kernel<<<cdiv(total, 256), 256>>>(
            v, rp, col, deg_inv, sterm, out, N, F4, relu);
    } else {
        long long total = (long long)N * F;
        gather_mean_kernel<<<cdiv(total, 256), 256>>>(
            v, rp, col, deg_inv, sterm, out, N, F, relu);
    }
}

extern "C" void kernel_launch(void* const* d_in, const int* in_sizes, int n_in,
                              void* d_out, int out_size) {
    const float* x = (const float*)d_in[0];
    const void* edge_raw = d_in[1];
    const int N = in_sizes[0] / 768;
    const int E = in_sizes[1] / 2;

    const float* Wl[5]; const float* Wr[5]; const float* bb[5];
    for (int li = 0; li < 5; li++) {
        Wl[li] = (const float*)d_in[2 + 3 * li];
        Wr[li] = (const float*)d_in[3 + 3 * li];
        bb[li] = (const float*)d_in[4 + 3 * li];
    }

    float *deg_inv, *bufH, *bufV, *bufS, *bufA;
    int *src, *dst, *cnt, *row_ptr, *cursor, *col;
    cudaGetSymbolAddress((void**)&deg_inv, g_deg_inv);
    cudaGetSymbolAddress((void**)&bufH,    g_bufH);
    cudaGetSymbolAddress((void**)&bufV,    g_bufV);
    cudaGetSymbolAddress((void**)&bufS,    g_bufS);
    cudaGetSymbolAddress((void**)&bufA,    g_bufA);
    cudaGetSymbolAddress((void**)&src,     g_src);
    cudaGetSymbolAddress((void**)&dst,     g_dst);
    cudaGetSymbolAddress((void**)&cnt,     g_cnt);
    cudaGetSymbolAddress((void**)&row_ptr, g_row_ptr);
    cudaGetSymbolAddress((void**)&cursor,  g_cursor);
    cudaGetSymbolAddress((void**)&col,     g_col);

    float* out_h = (float*)d_out;                    // [N, 256]
    float* out_y = (float*)d_out + (size_t)N * 256;  // [N, 5]

    // ---- edge index conversion (int32 or int64 storage) ----
    detect_kernel<<<1, 32>>>((const int*)edge_raw);
    convert_kernel<<<cdiv(E, 256), 256>>>(edge_raw, src, dst, E);

    // ---- CSR build (dst-grouped) + deg_inv ----
    cudaMemsetAsync(cnt, 0, (size_t)(N + 1) * sizeof(int), 0);
    cudaMemsetAsync(cursor, 0, (size_t)N * sizeof(int), 0);
    count_kernel<<<cdiv(E, 256), 256>>>(dst, cnt, E);
    deg_inv_kernel<<<cdiv(N, 256), 256>>>(cnt, deg_inv, N);
    scan_kernel<<<1, 1024>>>(cnt, row_ptr, N);
    fill_kernel<<<cdiv(E, 256), 256>>>(src, dst, row_ptr, cursor, col, E);

    // ---- Layer 1 (768 -> 1536): aggregate-first ----
    // bufA = mean-gather(x); h1 = relu(bufA @ Wl1 + x @ Wr1 + b1)
    launch_gather(x, row_ptr, col, deg_inv, nullptr, bufA, N, 768, 0);
    {
        dim3 grid(1536 / 128, cdiv(N, 128));
        tgemm_dual<<<grid, 256>>>(bufA, Wl[0], x, Wr[0], bb[0], bufH,
                                  N, 768, 1536, 1);
    }

    // ---- Layers 2..5: transform-then-aggregate ----
    const int dims_in[4]  = {1536, 768, 384, 256};
    const int dims_out[4] = {768, 384, 256, 5};
    const float* hin = bufH;
    for (int li = 1; li < 5; li++) {
        int K = dims_in[li - 1];
        int M = dims_out[li - 1];
        if (M % 128 == 0 && K % 16 == 0) {
            // one launch computes V = h@Wl and S = h@Wr + b
            dim3 grid(2 * (M / 128), cdiv(N, 128));
            tgemm_pair<<<grid, 256>>>(hin, Wl[li], Wr[li], bb[li],
                                      bufV, bufS, N, K, M);
        } else {
            dim3 grid(cdiv(M, 64), cdiv(N, 64));
            gemm_small<<<grid, 256>>>(hin, Wl[li], nullptr, bufV, N, K, M);
            gemm_small<<<grid, 256>>>(hin, Wr[li], bb[li],  bufS, N, K, M);
        }
        // out = maybe_relu(mean-gather(V) + S)
        if (li == 3) {
            launch_gather(bufV, row_ptr, col, deg_inv, bufS, out_h, N, M, 1);
            hin = out_h;
        } else if (li == 4) {
            launch_gather(bufV, row_ptr, col, deg_inv, bufS, out_y, N, M, 0);
        } else {
            launch_gather(bufV, row_ptr, col, deg_inv, bufS, bufH, N, M, 1);
            hin = bufH;
        }
    }
}